// round 8
// baseline (speedup 1.0000x reference)
#include <cuda_runtime.h>
#include <cuda_bf16.h>
#include <math.h>

#define B_ 32
#define T_ 64
#define N_ 128
#define D_ 64
#define K2 129              // 2D+1 (source layout)
#define KD (K2*D_)          // 8256 (source stride)
#define KR 132              // padded k rows: [x 0..63 | rs 64 | pad 65..67 | h 68..131]
#define KD132 (KR*D_)       // 8448
#define HSZ (B_*N_*D_)
#define GRID 128
#define BLOCK 1024

// ---- smem layout (floats) ----
#define OFF_W     0                    // 3*KD132 persistent Weff (r,u,c)
#define OFF_BEFF  (3*KD132)            // 192
#define OFF_S     (3*KD132 + 192)
// Phase A scratch (rel OFF_S)
#define A_FEAT    0                    // 128*132 = 16896
#define A_WT      16896                // 128*32 = 4096
#define A_RSV     20992                // 128
#define A_LIST    21120                // 128 ints
#define A_CNT     21248                // 8 ints
// Phase B scratch (rel OFF_S)
#define B_COMB    0                    // 32*132 = 4224
#define B_ZCS     4224                 // 32*132 = 4224  (x|rs|pad|h1)
#define B_HS      8448                 // 2048
#define B_US      10496                // 2048
#define B_CX      12544                // 2048
#define B_MS      14592                // 32
#define B_LISTB   14624                // 32 ints
#define B_LISTU   14656                // 32 ints
#define B_LEN     14688                // 32 ints
#define B_PNB     14720                // 1
#define SCR_FLOATS 21256
#define SMEM_FLOATS (OFF_S + SCR_FLOATS)
#define SMEM_BYTES  (SMEM_FLOATS*4 + 128)

__device__ float g_invtot[B_*N_];
__device__ float g_hbuf[2*HSZ];
__device__ float g_comb[B_*N_*KR];   // pad rows (65..67) never written; stay zero
__device__ float g_P[N_*N_];         // P[j][i] = adjI[i][j]
__device__ float g_Q[N_*N_];         // Q[j][i] = adjI[i][j]*rarW[i][j]

// ---- two-level grid barrier ----
__device__ unsigned int g_cnt[8*32];
__device__ unsigned int g_rootc;
__device__ volatile unsigned int g_gen;

__device__ __forceinline__ void grid_barrier() {
    __syncthreads();
    if (threadIdx.x == 0) {
        __threadfence();
        unsigned int gen = g_gen;
        unsigned int grp = blockIdx.x >> 4;
        unsigned int o = atomicAdd(&g_cnt[grp*32], 1u);
        if ((o & 15u) == 15u) {
            unsigned int r = atomicAdd(&g_rootc, 1u);
            if ((r & 7u) == 7u) {
                __threadfence();
                g_gen = gen + 1u;
            }
        }
        while (g_gen == gen) { }
        __threadfence();
    }
    __syncthreads();
}

__device__ __forceinline__ float tanhfast(float x) {
    float y;
    asm("tanh.approx.f32 %0, %1;" : "=f"(y) : "f"(x));
    return y;
}
__device__ __forceinline__ float sigfast(float x) {
    return fmaf(tanhfast(0.5f*x), 0.5f, 0.5f);
}

__global__ void __launch_bounds__(BLOCK, 1)
cgrnn_persistent(const float* __restrict__ obs,      // [B,T,N,D]
                 const float* __restrict__ mask,     // [B,T,N]
                 const int*   __restrict__ lengths,  // [B]
                 const float* __restrict__ avg,      // [B,T,N]
                 const float* __restrict__ vpe,      // [N,768]
                 const float* __restrict__ rarW,     // [N,N]
                 const float* __restrict__ adjI,     // [N,N]
                 const float* __restrict__ W1,       // [768,128]
                 const float* __restrict__ b1,       // [128]
                 const float* __restrict__ W2,       // [128,5]
                 const float* __restrict__ b2,       // [5]
                 const float* __restrict__ Wr, const float* __restrict__ brp,
                 const float* __restrict__ Wu, const float* __restrict__ bup,
                 const float* __restrict__ Wc, const float* __restrict__ bcp,
                 float* __restrict__ out)            // [B,N,D]
{
    extern __shared__ char smem_raw[];
    float* sm = (float*)smem_raw;
    float* Wst    = sm + OFF_W;
    float* beff_s = sm + OFF_BEFF;
    float* scr    = sm + OFF_S;
    const int tid  = threadIdx.x;
    const int bid  = blockIdx.x;
    const int warp = tid >> 5;
    const int lane = tid & 31;
    const int n_node = bid;

    // ========== P1: hypernetwork vv for this node ==========
    {
        float* part = scr;
        float* hid  = scr + 1024;
        float* vvs  = scr + 1152;
        int q = tid >> 7, col = tid & 127;
        const float* vrow = vpe + n_node*768;
        float acc = 0.0f;
        int k0 = q * 96;
        #pragma unroll 4
        for (int k = k0; k < k0 + 96; k++)
            acc = fmaf(vrow[k], W1[k*128 + col], acc);
        part[tid] = acc;
        __syncthreads();
        if (tid < 128) {
            float h = b1[tid];
            #pragma unroll
            for (int qq = 0; qq < 8; qq++) h += part[qq*128 + tid];
            hid[tid] = fmaxf(h, 0.0f);
        }
        __syncthreads();
        if (tid < 5) {
            float a = b2[tid];
            for (int d = 0; d < 128; d++)
                a = fmaf(hid[d], W2[d*5 + tid], a);
            vvs[tid] = a;
        }
        __syncthreads();

        // ===== P2a: effective weights in padded k-order [x|rs|pad3|h] =====
        float v0 = vvs[0], v1 = vvs[1], v2 = vvs[2], v3 = vvs[3], v4 = vvs[4];
        for (int idx = tid; idx < 3*KD132; idx += BLOCK) {
            int g  = idx / KD132;
            int kd = idx - g*KD132;
            int kk = kd >> 6;
            int d  = kd & 63;
            float a = 0.0f;
            if (kk < 65 || kk >= 68) {
                int ko = (kk < 65) ? kk : (kk - 3);
                const float* src = (g == 0) ? Wr : (g == 1) ? Wu : Wc;
                int off = ko*64 + d;
                a = v0 * src[off];
                a = fmaf(v1, src[KD + off], a);
                a = fmaf(v2, src[2*KD + off], a);
                a = fmaf(v3, src[3*KD + off], a);
                a = fmaf(v4, src[4*KD + off], a);
            }
            Wst[idx] = a;
        }
        for (int idx = tid; idx < 3*D_; idx += BLOCK) {
            int g = idx >> 6;
            int d = idx & 63;
            const float* src = (g == 0) ? brp : (g == 1) ? bup : bcp;
            float a = v0 * src[d];
            a = fmaf(v1, src[D_ + d], a);
            a = fmaf(v2, src[2*D_ + d], a);
            a = fmaf(v3, src[3*D_ + d], a);
            a = fmaf(v4, src[4*D_ + d], a);
            beff_s[idx] = a;
        }
    }

    // ===== P2b: inv_tot, P/Q transpose, zero h0 =====
    {
        for (int k = tid; k < 32; k += BLOCK) {
            int idx = bid*32 + k;
            int b = idx >> 7;
            int n = idx & 127;
            float s = 0.0f;
            for (int t = 0; t < T_; t++) s += mask[(b*T_ + t)*N_ + n];
            g_invtot[idx] = 1.0f / (s + 1.0f);
        }
        for (int idx = bid*BLOCK + tid; idx < N_*N_; idx += GRID*BLOCK) {
            int j = idx >> 7, i = idx & 127;
            float a = adjI[i*N_ + j];
            g_P[idx] = a;
            g_Q[idx] = a * rarW[i*N_ + j];
        }
        for (int idx = bid*BLOCK + tid; idx < HSZ; idx += GRID*BLOCK)
            g_hbuf[idx] = 0.0f;
    }
    grid_barrier();

    // ========== time loop ==========
    for (int t = 0; t < T_; t++) {
        const float* hprev = g_hbuf + (t & 1) * HSZ;
        float*       hnext = g_hbuf + ((t + 1) & 1) * HSZ;

        // ---------------- Phase A ----------------
        {
            const int b = bid >> 2;
            const int q = bid & 3;
            float* feat = scr + A_FEAT;
            float* wT   = scr + A_WT;
            float* rsv  = scr + A_RSV;
            int*   list = (int*)(scr + A_LIST);
            int*   cnt  = (int*)(scr + A_CNT);

            if (tid < 128) {
                float m = mask[(b*T_ + t)*N_ + tid];
                rsv[tid] = 0.5f * tanhfast(avg[(b*T_ + t)*N_ + tid] * g_invtot[b*N_ + tid]);
                bool ob = (m != 0.0f);
                unsigned msk = __ballot_sync(0xffffffffu, ob);
                if (lane == 0) { cnt[warp] = __popc(msk); ((unsigned*)cnt)[4 + warp] = msk; }
            }
            __syncthreads();
            const int nobs = cnt[0] + cnt[1] + cnt[2] + cnt[3];
            if (tid < 128) {
                unsigned msk = ((unsigned*)cnt)[4 + warp];
                if ((msk >> lane) & 1u) {
                    int off = __popc(msk & ((1u << lane) - 1u));
                    for (int ww = 0; ww < warp; ww++) off += cnt[ww];
                    list[off] = tid;
                }
            }
            __syncthreads();

            const int lo  = (nobs * q) >> 2;
            const int hi  = (nobs * (q + 1)) >> 2;
            const int myn = hi - lo;

            // stage feat: x at 0..63, rs at 64, pads 65..67, h at 68..131
            for (int idx = tid; idx < nobs*16; idx += BLOCK) {
                int jc = idx >> 4, qq = idx & 15;
                int j = list[jc];
                *(float4*)(feat + jc*KR + qq*4) =
                    *(const float4*)(obs + (size_t)((b*T_ + t)*N_ + j)*D_ + qq*4);
            }
            for (int idx = tid; idx < nobs*16; idx += BLOCK) {
                int jc = idx >> 4, qq = idx & 15;
                int j = list[jc];
                *(float4*)(feat + jc*KR + 68 + qq*4) =
                    *(const float4*)(hprev + (size_t)(b*N_ + j)*D_ + qq*4);
            }
            if (tid < nobs) {
                float* fr = feat + tid*KR;
                fr[64] = rsv[list[tid]];
                fr[65] = 0.0f; fr[66] = 0.0f; fr[67] = 0.0f;
            }
            // stage wT[jc][ic] (lane = ic, conflict-free)
            {
                int jc0 = warp;
                int ic  = lane;
                int i   = (ic < myn) ? list[lo + ic] : 0;
                float rsi = rsv[i];
                bool valid = (ic < myn);
                for (int jc = jc0; jc < nobs; jc += 32) {
                    int j = list[jc];
                    float wv = 0.0f;
                    if (valid) {
                        if (j == i) wv = 1.0f;
                        else wv = g_P[j*N_ + i] - g_Q[j*N_ + i] * fabsf(rsi - rsv[j]);
                    }
                    wT[jc*32 + ic] = wv;
                }
            }
            __syncthreads();

            // GEMM: 2-row x 1-col tiles
            const int RG2 = (myn + 1) >> 1;
            for (int tt = tid; tt < RG2*129; tt += BLOCK) {
                int rg = tt / 129;
                int cc = tt - rg*129;
                int c  = (cc < 65) ? cc : (cc + 3);
                const float* wp = wT + rg*2;
                const float* fp = feat + c;
                float ax = 0.0f, ay = 0.0f;
                #pragma unroll 4
                for (int jc = 0; jc < nobs; jc++) {
                    float fv = fp[jc*KR];
                    float2 w2 = *(const float2*)(wp + jc*32);
                    ax = fmaf(w2.x, fv, ax);
                    ay = fmaf(w2.y, fv, ay);
                }
                int ic0 = rg*2;
                {
                    int i = list[lo + ic0];
                    g_comb[(size_t)(b*N_ + i)*KR + c] = ax;
                }
                if (ic0 + 1 < myn) {
                    int i = list[lo + ic0 + 1];
                    g_comb[(size_t)(b*N_ + i)*KR + c] = ay;
                }
            }
        }
        grid_barrier();

        // ---------------- Phase B ----------------
        {
            const int n = n_node;
            float* combs = scr + B_COMB;
            float* zcs   = scr + B_ZCS;
            float* hs    = scr + B_HS;
            float* us    = scr + B_US;
            float* cxs   = scr + B_CX;
            float* ms    = scr + B_MS;
            int*   listB = (int*)(scr + B_LISTB);
            int*   listU = (int*)(scr + B_LISTU);
            int*   lenS  = (int*)(scr + B_LEN);
            int*   pnB   = (int*)(scr + B_PNB);

            if (tid < 32) {
                int b = tid;
                float m = mask[(b*T_ + t)*N_ + n];
                ms[b] = m;
                float* zr = zcs + b*KR;
                zr[64] = 0.5f * tanhfast(avg[(b*T_ + t)*N_ + n] * g_invtot[b*N_ + n]);
                zr[65] = 0.0f; zr[66] = 0.0f; zr[67] = 0.0f;
                lenS[b] = lengths[b];
                bool ob = (m != 0.0f);
                unsigned msk = __ballot_sync(0xffffffffu, ob);
                unsigned msku = ~msk;
                if (ob) listB[__popc(msk & ((1u << tid) - 1u))] = b;
                else    listU[__popc(msku & ((1u << tid) - 1u))] = b;
                if (tid == 0) *pnB = __popc(msk);
            }
            for (int idx = tid; idx < (B_*D_)/4; idx += BLOCK) {
                int b = idx >> 4, qq = idx & 15;
                *(float4*)(hs + b*64 + qq*4) =
                    *(const float4*)(hprev + (size_t)(b*N_ + n)*D_ + qq*4);
            }
            __syncthreads();
            const int nB = *pnB;
            const int BQ  = (nB + 3) >> 2;   // batch quads
            const int BP2 = (nB + 1) >> 1;   // batch pairs

            for (int idx = tid; idx < nB*33; idx += BLOCK) {
                int bc = idx / 33;
                int qq = idx - bc*33;
                int b  = listB[bc];
                *(float4*)(combs + b*KR + qq*4) =
                    *(const float4*)(g_comb + (size_t)(b*N_ + n)*KR + qq*4);
            }
            for (int idx = tid; idx < nB*16; idx += BLOCK) {
                int bc = idx >> 4, qq = idx & 15;
                int b  = listB[bc];
                *(float4*)(zcs + b*KR + qq*4) =
                    *(const float4*)(obs + (size_t)((b*T_ + t)*N_ + n)*D_ + qq*4);
            }
            __syncthreads();

            // ---- pass1 warp-tasks ----
            // [0, 4*BQ): r/u on a batch-quad, d-half; lane = 1 dim, 4 accs
            // [4*BQ, 4*BQ + 2*BP2): candx on a batch-pair, d-half (k = 0..64)
            const int NT_RU = 4*BQ;
            const int NT1 = NT_RU + 2*BP2;
            for (int tau = warp; tau < NT1; tau += 32) {
                if (tau < NT_RU) {
                    int bq  = tau >> 2;
                    int sub = tau & 3;
                    int g   = sub >> 1;          // 0=r, 1=u
                    int dh  = sub & 1;
                    int d   = dh*32 + lane;
                    int b0 = listB[min(4*bq + 0, nB - 1)];
                    int b1 = listB[min(4*bq + 1, nB - 1)];
                    int b2 = listB[min(4*bq + 2, nB - 1)];
                    int b3 = listB[min(4*bq + 3, nB - 1)];
                    const float* W = Wst + g*KD132 + d;
                    const float4* p0 = (const float4*)(combs + b0*KR);
                    const float4* p1 = (const float4*)(combs + b1*KR);
                    const float4* p2 = (const float4*)(combs + b2*KR);
                    const float4* p3 = (const float4*)(combs + b3*KR);
                    float bias = beff_s[g*64 + d];
                    float a0 = bias, a1 = bias, a2 = bias, a3 = bias;
                    #pragma unroll 3
                    for (int k4 = 0; k4 < 33; k4++) {
                        float4 c0 = p0[k4], c1 = p1[k4], c2 = p2[k4], c3 = p3[k4];
                        float w0 = W[(k4*4 + 0)*64];
                        float w1 = W[(k4*4 + 1)*64];
                        float w2 = W[(k4*4 + 2)*64];
                        float w3 = W[(k4*4 + 3)*64];
                        a0 = fmaf(c0.x, w0, a0); a0 = fmaf(c0.y, w1, a0);
                        a0 = fmaf(c0.z, w2, a0); a0 = fmaf(c0.w, w3, a0);
                        a1 = fmaf(c1.x, w0, a1); a1 = fmaf(c1.y, w1, a1);
                        a1 = fmaf(c1.z, w2, a1); a1 = fmaf(c1.w, w3, a1);
                        a2 = fmaf(c2.x, w0, a2); a2 = fmaf(c2.y, w1, a2);
                        a2 = fmaf(c2.z, w2, a2); a2 = fmaf(c2.w, w3, a2);
                        a3 = fmaf(c3.x, w0, a3); a3 = fmaf(c3.y, w1, a3);
                        a3 = fmaf(c3.z, w2, a3); a3 = fmaf(c3.w, w3, a3);
                    }
                    if (g == 0) {
                        zcs[b0*KR + 68 + d] = sigfast(a0) * hs[b0*64 + d];
                        zcs[b1*KR + 68 + d] = sigfast(a1) * hs[b1*64 + d];
                        zcs[b2*KR + 68 + d] = sigfast(a2) * hs[b2*64 + d];
                        zcs[b3*KR + 68 + d] = sigfast(a3) * hs[b3*64 + d];
                    } else {
                        us[b0*64 + d] = sigfast(a0);
                        us[b1*64 + d] = sigfast(a1);
                        us[b2*64 + d] = sigfast(a2);
                        us[b3*64 + d] = sigfast(a3);
                    }
                } else {
                    int t2 = tau - NT_RU;
                    int bp = t2 >> 1;
                    int dh = t2 & 1;
                    int d  = dh*32 + lane;
                    int b0 = listB[2*bp];
                    int b1 = listB[min(2*bp + 1, nB - 1)];
                    const float* W = Wst + 2*KD132 + d;
                    const float4* p0 = (const float4*)(zcs + b0*KR);
                    const float4* p1 = (const float4*)(zcs + b1*KR);
                    float bias = beff_s[2*64 + d];
                    float a0 = bias, a1 = bias;
                    #pragma unroll 4
                    for (int k4 = 0; k4 < 16; k4++) {
                        float4 c0 = p0[k4], c1 = p1[k4];
                        float w0 = W[(k4*4 + 0)*64];
                        float w1 = W[(k4*4 + 1)*64];
                        float w2 = W[(k4*4 + 2)*64];
                        float w3 = W[(k4*4 + 3)*64];
                        a0 = fmaf(c0.x, w0, a0); a0 = fmaf(c0.y, w1, a0);
                        a0 = fmaf(c0.z, w2, a0); a0 = fmaf(c0.w, w3, a0);
                        a1 = fmaf(c1.x, w0, a1); a1 = fmaf(c1.y, w1, a1);
                        a1 = fmaf(c1.z, w2, a1); a1 = fmaf(c1.w, w3, a1);
                    }
                    float rs0 = zcs[b0*KR + 64];
                    float rs1 = zcs[b1*KR + 64];
                    float wrs = W[64*64];
                    a0 = fmaf(rs0, wrs, a0);
                    a1 = fmaf(rs1, wrs, a1);
                    cxs[b0*64 + d] = a0;
                    cxs[b1*64 + d] = a1;
                }
            }
            __syncthreads();

            // ---- pass2: candh on batch-pairs, d-half; carry unobserved ----
            const int NT2 = 2*BP2 + (B_ - nB);
            for (int tau = warp; tau < NT2; tau += 32) {
                if (tau < 2*BP2) {
                    int bp = tau >> 1;
                    int dh = tau & 1;
                    int d  = dh*32 + lane;
                    int b0 = listB[2*bp];
                    int b1 = listB[min(2*bp + 1, nB - 1)];
                    const float* W = Wst + 2*KD132 + 68*64 + d;
                    const float4* p0 = (const float4*)(zcs + b0*KR + 68);
                    const float4* p1 = (const float4*)(zcs + b1*KR + 68);
                    float a0 = cxs[b0*64 + d];
                    float a1 = cxs[b1*64 + d];
                    #pragma unroll 4
                    for (int k4 = 0; k4 < 16; k4++) {
                        float4 c0 = p0[k4], c1 = p1[k4];
                        float w0 = W[(k4*4 + 0)*64];
                        float w1 = W[(k4*4 + 1)*64];
                        float w2 = W[(k4*4 + 2)*64];
                        float w3 = W[(k4*4 + 3)*64];
                        a0 = fmaf(c0.x, w0, a0); a0 = fmaf(c0.y, w1, a0);
                        a0 = fmaf(c0.z, w2, a0); a0 = fmaf(c0.w, w3, a0);
                        a1 = fmaf(c1.x, w0, a1); a1 = fmaf(c1.y, w1, a1);
                        a1 = fmaf(c1.z, w2, a1); a1 = fmaf(c1.w, w3, a1);
                    }
                    float h10 = zcs[b0*KR + 68 + d];
                    float h11 = zcs[b1*KR + 68 + d];
                    float u0  = us[b0*64 + d];
                    float u1  = us[b1*64 + d];
                    float v0 = h10 + u0 * (tanhfast(a0) - h10);
                    float v1 = h11 + u1 * (tanhfast(a1) - h11);
                    hnext[(size_t)(b0*N_ + n)*D_ + d] = v0;
                    hnext[(size_t)(b1*N_ + n)*D_ + d] = v1;
                    if (t == lenS[b0] - 1) out[(size_t)(b0*N_ + n)*D_ + d] = v0;
                    if (t == lenS[b1] - 1) out[(size_t)(b1*N_ + n)*D_ + d] = v1;
                } else {
                    int iu = tau - 2*BP2;
                    int b = listU[iu];
                    int d0 = lane*2;
                    float2 v = *(const float2*)(hs + b*64 + d0);
                    *(float2*)(hnext + (size_t)(b*N_ + n)*D_ + d0) = v;
                    if (t == lenS[b] - 1)
                        *(float2*)(out + (size_t)(b*N_ + n)*D_ + d0) = v;
                }
            }
        }
        grid_barrier();
    }
}

extern "C" void kernel_launch(void* const* d_in, const int* in_sizes, int n_in,
                              void* d_out, int out_size) {
    const float* obs     = (const float*)d_in[0];
    const float* mask    = (const float*)d_in[2];
    const int*   lengths = (const int*)d_in[5];
    const float* avg     = (const float*)d_in[6];
    const float* vpe     = (const float*)d_in[7];
    const float* rarW    = (const float*)d_in[8];
    const float* adjI    = (const float*)d_in[9];
    const float* W1      = (const float*)d_in[10];
    const float* b1      = (const float*)d_in[11];
    const float* W2      = (const float*)d_in[12];
    const float* b2      = (const float*)d_in[13];
    const float* Wu      = (const float*)d_in[14];
    const float* bu      = (const float*)d_in[15];
    const float* Wr      = (const float*)d_in[16];
    const float* br      = (const float*)d_in[17];
    const float* Wc      = (const float*)d_in[18];
    const float* bc      = (const float*)d_in[19];
    float* out = (float*)d_out;

    cudaFuncSetAttribute(cgrnn_persistent,
                         cudaFuncAttributeMaxDynamicSharedMemorySize, SMEM_BYTES);
    cgrnn_persistent<<<GRID, BLOCK, SMEM_BYTES>>>(
        obs, mask, lengths, avg, vpe, rarW, adjI,
        W1, b1, W2, b2, Wr, br, Wu, bu, Wc, bc, out);
}

// round 9
// speedup vs baseline: 1.0615x; 1.0615x over previous
#include <cuda_runtime.h>
#include <cuda_bf16.h>
#include <math.h>

#define B_ 32
#define T_ 64
#define N_ 128
#define D_ 64
#define K2 129              // 2D+1 (source layout)
#define KD (K2*D_)          // 8256 (source stride)
#define KR 132              // padded k rows: [x 0..63 | rs 64 | pad 65..67 | h 68..131]
#define KD132 (KR*D_)       // 8448
#define HSZ (B_*N_*D_)
#define GRID 128
#define BLOCK 1024

// ---- smem layout (floats) ----
// Wt layout: Wt[g][d][k] : g*KD132 + d*132 + k   (k-contiguous, odd float4 stride)
#define OFF_W     0                    // 3*KD132 persistent Weff (r,u,c) transposed
#define OFF_BEFF  (3*KD132)            // 192
#define OFF_S     (3*KD132 + 192)
// Phase A scratch (rel OFF_S)
#define A_FEAT    0                    // 128*132 = 16896
#define A_WT      16896                // 128*32 = 4096
#define A_RSV     20992                // 128
#define A_LIST    21120                // 128 ints
#define A_CNT     21248                // 8 ints
// Phase B scratch (rel OFF_S)
#define B_COMB    0                    // 32*132 = 4224
#define B_ZCS     4224                 // 32*132 = 4224  (x|rs|pad|h1)
#define B_HS      8448                 // 2048
#define B_US      10496                // 2048
#define B_CX      12544                // 2048
#define B_MS      14592                // 32
#define B_LISTB   14624                // 32 ints
#define B_LISTU   14656                // 32 ints
#define B_LEN     14688                // 32 ints
#define B_PNB     14720                // 1
#define SCR_FLOATS 21256
#define SMEM_FLOATS (OFF_S + SCR_FLOATS)
#define SMEM_BYTES  (SMEM_FLOATS*4 + 128)

__device__ float g_invtot[B_*N_];
__device__ float g_hbuf[2*HSZ];
__device__ float g_comb[B_*N_*KR];   // pad rows (65..67) stay zero
__device__ float g_P[N_*N_];         // P[j][i] = adjI[i][j]
__device__ float g_Q[N_*N_];         // Q[j][i] = adjI[i][j]*rarW[i][j]

// ---- two-level grid barrier ----
__device__ unsigned int g_cnt[8*32];
__device__ unsigned int g_rootc;
__device__ volatile unsigned int g_gen;

__device__ __forceinline__ void grid_barrier() {
    __syncthreads();
    if (threadIdx.x == 0) {
        __threadfence();
        unsigned int gen = g_gen;
        unsigned int grp = blockIdx.x >> 4;
        unsigned int o = atomicAdd(&g_cnt[grp*32], 1u);
        if ((o & 15u) == 15u) {
            unsigned int r = atomicAdd(&g_rootc, 1u);
            if ((r & 7u) == 7u) {
                __threadfence();
                g_gen = gen + 1u;
            }
        }
        while (g_gen == gen) { }
        __threadfence();
    }
    __syncthreads();
}

__device__ __forceinline__ float tanhfast(float x) {
    float y;
    asm("tanh.approx.f32 %0, %1;" : "=f"(y) : "f"(x));
    return y;
}
__device__ __forceinline__ float sigfast(float x) {
    return fmaf(tanhfast(0.5f*x), 0.5f, 0.5f);
}

__global__ void __launch_bounds__(BLOCK, 1)
cgrnn_persistent(const float* __restrict__ obs,      // [B,T,N,D]
                 const float* __restrict__ mask,     // [B,T,N]
                 const int*   __restrict__ lengths,  // [B]
                 const float* __restrict__ avg,      // [B,T,N]
                 const float* __restrict__ vpe,      // [N,768]
                 const float* __restrict__ rarW,     // [N,N]
                 const float* __restrict__ adjI,     // [N,N]
                 const float* __restrict__ W1,       // [768,128]
                 const float* __restrict__ b1,       // [128]
                 const float* __restrict__ W2,       // [128,5]
                 const float* __restrict__ b2,       // [5]
                 const float* __restrict__ Wr, const float* __restrict__ brp,
                 const float* __restrict__ Wu, const float* __restrict__ bup,
                 const float* __restrict__ Wc, const float* __restrict__ bcp,
                 float* __restrict__ out)            // [B,N,D]
{
    extern __shared__ char smem_raw[];
    float* sm = (float*)smem_raw;
    float* Wst    = sm + OFF_W;
    float* beff_s = sm + OFF_BEFF;
    float* scr    = sm + OFF_S;
    const int tid  = threadIdx.x;
    const int bid  = blockIdx.x;
    const int warp = tid >> 5;
    const int lane = tid & 31;
    const int n_node = bid;

    // ========== P1: hypernetwork vv for this node ==========
    {
        float* part = scr;
        float* hid  = scr + 1024;
        float* vvs  = scr + 1152;
        int q = tid >> 7, col = tid & 127;
        const float* vrow = vpe + n_node*768;
        float acc = 0.0f;
        int k0 = q * 96;
        #pragma unroll 4
        for (int k = k0; k < k0 + 96; k++)
            acc = fmaf(vrow[k], W1[k*128 + col], acc);
        part[tid] = acc;
        __syncthreads();
        if (tid < 128) {
            float h = b1[tid];
            #pragma unroll
            for (int qq = 0; qq < 8; qq++) h += part[qq*128 + tid];
            hid[tid] = fmaxf(h, 0.0f);
        }
        __syncthreads();
        if (tid < 5) {
            float a = b2[tid];
            for (int d = 0; d < 128; d++)
                a = fmaf(hid[d], W2[d*5 + tid], a);
            vvs[tid] = a;
        }
        __syncthreads();

        // ===== P2a: effective weights, TRANSPOSED Wt[g][d][k], k padded =====
        float v0 = vvs[0], v1 = vvs[1], v2 = vvs[2], v3 = vvs[3], v4 = vvs[4];
        for (int idx = tid; idx < 3*KD132; idx += BLOCK) {
            int g  = idx / KD132;
            int kd = idx - g*KD132;
            int kk = kd >> 6;     // padded k 0..131
            int d  = kd & 63;
            float a = 0.0f;
            if (kk < 65 || kk >= 68) {
                int ko = (kk < 65) ? kk : (kk - 3);
                const float* src = (g == 0) ? Wr : (g == 1) ? Wu : Wc;
                int off = ko*64 + d;
                a = v0 * src[off];
                a = fmaf(v1, src[KD + off], a);
                a = fmaf(v2, src[2*KD + off], a);
                a = fmaf(v3, src[3*KD + off], a);
                a = fmaf(v4, src[4*KD + off], a);
            }
            Wst[g*KD132 + d*132 + kk] = a;
        }
        for (int idx = tid; idx < 3*D_; idx += BLOCK) {
            int g = idx >> 6;
            int d = idx & 63;
            const float* src = (g == 0) ? brp : (g == 1) ? bup : bcp;
            float a = v0 * src[d];
            a = fmaf(v1, src[D_ + d], a);
            a = fmaf(v2, src[2*D_ + d], a);
            a = fmaf(v3, src[3*D_ + d], a);
            a = fmaf(v4, src[4*D_ + d], a);
            beff_s[idx] = a;
        }
    }

    // ===== P2b: inv_tot, P/Q transpose, zero h0 =====
    {
        for (int k = tid; k < 32; k += BLOCK) {
            int idx = bid*32 + k;
            int b = idx >> 7;
            int n = idx & 127;
            float s = 0.0f;
            for (int t = 0; t < T_; t++) s += mask[(b*T_ + t)*N_ + n];
            g_invtot[idx] = 1.0f / (s + 1.0f);
        }
        for (int idx = bid*BLOCK + tid; idx < N_*N_; idx += GRID*BLOCK) {
            int j = idx >> 7, i = idx & 127;
            float a = adjI[i*N_ + j];
            g_P[idx] = a;
            g_Q[idx] = a * rarW[i*N_ + j];
        }
        for (int idx = bid*BLOCK + tid; idx < HSZ; idx += GRID*BLOCK)
            g_hbuf[idx] = 0.0f;
    }
    grid_barrier();

    // ========== time loop ==========
    for (int t = 0; t < T_; t++) {
        const float* hprev = g_hbuf + (t & 1) * HSZ;
        float*       hnext = g_hbuf + ((t + 1) & 1) * HSZ;

        // ---------------- Phase A ----------------
        {
            const int b = bid >> 2;
            const int q = bid & 3;
            float* feat = scr + A_FEAT;
            float* wT   = scr + A_WT;
            float* rsv  = scr + A_RSV;
            int*   list = (int*)(scr + A_LIST);
            int*   cnt  = (int*)(scr + A_CNT);

            if (tid < 128) {
                float m = mask[(b*T_ + t)*N_ + tid];
                rsv[tid] = 0.5f * tanhfast(avg[(b*T_ + t)*N_ + tid] * g_invtot[b*N_ + tid]);
                bool ob = (m != 0.0f);
                unsigned msk = __ballot_sync(0xffffffffu, ob);
                if (lane == 0) { cnt[warp] = __popc(msk); ((unsigned*)cnt)[4 + warp] = msk; }
            }
            __syncthreads();
            const int nobs = cnt[0] + cnt[1] + cnt[2] + cnt[3];
            if (tid < 128) {
                unsigned msk = ((unsigned*)cnt)[4 + warp];
                if ((msk >> lane) & 1u) {
                    int off = __popc(msk & ((1u << lane) - 1u));
                    for (int ww = 0; ww < warp; ww++) off += cnt[ww];
                    list[off] = tid;
                }
            }
            __syncthreads();

            const int lo  = (nobs * q) >> 2;
            const int hi  = (nobs * (q + 1)) >> 2;
            const int myn = hi - lo;

            // stage feat: x 0..63 | rs 64 | pads 65..67 | h 68..131
            for (int idx = tid; idx < nobs*16; idx += BLOCK) {
                int jc = idx >> 4, qq = idx & 15;
                int j = list[jc];
                *(float4*)(feat + jc*KR + qq*4) =
                    *(const float4*)(obs + (size_t)((b*T_ + t)*N_ + j)*D_ + qq*4);
            }
            for (int idx = tid; idx < nobs*16; idx += BLOCK) {
                int jc = idx >> 4, qq = idx & 15;
                int j = list[jc];
                *(float4*)(feat + jc*KR + 68 + qq*4) =
                    *(const float4*)(hprev + (size_t)(b*N_ + j)*D_ + qq*4);
            }
            if (tid < nobs) {
                float* fr = feat + tid*KR;
                fr[64] = rsv[list[tid]];
                fr[65] = 0.0f; fr[66] = 0.0f; fr[67] = 0.0f;
            }
            // stage wT[jc][ic] (lane = ic, conflict-free)
            {
                int jc0 = warp;
                int ic  = lane;
                int i   = (ic < myn) ? list[lo + ic] : 0;
                float rsi = rsv[i];
                bool valid = (ic < myn);
                for (int jc = jc0; jc < nobs; jc += 32) {
                    int j = list[jc];
                    float wv = 0.0f;
                    if (valid) {
                        if (j == i) wv = 1.0f;
                        else wv = g_P[j*N_ + i] - g_Q[j*N_ + i] * fabsf(rsi - rsv[j]);
                    }
                    wT[jc*32 + ic] = wv;
                }
            }
            __syncthreads();

            // GEMM: 2-row x 2-col tiles over 66 padded col-pairs (<=1024 tasks)
            const int RG2 = (myn + 1) >> 1;
            for (int tt = tid; tt < RG2*66; tt += BLOCK) {
                int rg = tt / 66;
                int e  = tt - rg*66;
                int c0 = e*2;                     // padded col (even)
                const float* wp = wT + rg*2;
                const float* fp = feat + c0;
                float ax = 0.f, ay = 0.f, bx = 0.f, by = 0.f;
                #pragma unroll 4
                for (int jc = 0; jc < nobs; jc++) {
                    float2 w2 = *(const float2*)(wp + jc*32);
                    float2 f2 = *(const float2*)(fp + jc*KR);
                    ax = fmaf(w2.x, f2.x, ax); ay = fmaf(w2.x, f2.y, ay);
                    bx = fmaf(w2.y, f2.x, bx); by = fmaf(w2.y, f2.y, by);
                }
                int ic0 = rg*2;
                {
                    int i = list[lo + ic0];
                    *(float2*)&g_comb[(size_t)(b*N_ + i)*KR + c0] = make_float2(ax, ay);
                }
                if (ic0 + 1 < myn) {
                    int i1 = list[lo + ic0 + 1];
                    *(float2*)&g_comb[(size_t)(b*N_ + i1)*KR + c0] = make_float2(bx, by);
                }
            }
        }
        grid_barrier();

        // ---------------- Phase B ----------------
        {
            const int n = n_node;
            float* combs = scr + B_COMB;
            float* zcs   = scr + B_ZCS;
            float* hs    = scr + B_HS;
            float* us    = scr + B_US;
            float* cxs   = scr + B_CX;
            float* ms    = scr + B_MS;
            int*   listB = (int*)(scr + B_LISTB);
            int*   listU = (int*)(scr + B_LISTU);
            int*   lenS  = (int*)(scr + B_LEN);
            int*   pnB   = (int*)(scr + B_PNB);

            if (tid < 32) {
                int b = tid;
                float m = mask[(b*T_ + t)*N_ + n];
                ms[b] = m;
                float* zr = zcs + b*KR;
                zr[64] = 0.5f * tanhfast(avg[(b*T_ + t)*N_ + n] * g_invtot[b*N_ + n]);
                zr[65] = 0.0f; zr[66] = 0.0f; zr[67] = 0.0f;
                lenS[b] = lengths[b];
                bool ob = (m != 0.0f);
                unsigned msk = __ballot_sync(0xffffffffu, ob);
                unsigned msku = ~msk;
                if (ob) listB[__popc(msk & ((1u << tid) - 1u))] = b;
                else    listU[__popc(msku & ((1u << tid) - 1u))] = b;
                if (tid == 0) *pnB = __popc(msk);
            }
            for (int idx = tid; idx < (B_*D_)/4; idx += BLOCK) {
                int b = idx >> 4, qq = idx & 15;
                *(float4*)(hs + b*64 + qq*4) =
                    *(const float4*)(hprev + (size_t)(b*N_ + n)*D_ + qq*4);
            }
            __syncthreads();
            const int nB = *pnB;
            const int BQ  = (nB + 3) >> 2;
            const int BO  = (nB + 7) >> 3;
            const int BP2 = (nB + 1) >> 1;

            for (int idx = tid; idx < nB*33; idx += BLOCK) {
                int bc = idx / 33;
                int qq = idx - bc*33;
                int b  = listB[bc];
                *(float4*)(combs + b*KR + qq*4) =
                    *(const float4*)(g_comb + (size_t)(b*N_ + n)*KR + qq*4);
            }
            for (int idx = tid; idx < nB*16; idx += BLOCK) {
                int bc = idx >> 4, qq = idx & 15;
                int b  = listB[bc];
                *(float4*)(zcs + b*KR + qq*4) =
                    *(const float4*)(obs + (size_t)((b*T_ + t)*N_ + n)*D_ + qq*4);
            }
            __syncthreads();

            // ---- pass1 warp-tasks (r/u quads first; candx octets after) ----
            const int NT_RU = 4*BQ;            // <= 32
            const int NT1 = NT_RU + 2*BO;      // overflow only for nB>=25 (rare)
            for (int tau = warp; tau < NT1; tau += 32) {
                if (tau < NT_RU) {
                    int bq  = tau >> 2;
                    int sub = tau & 3;
                    int g   = sub >> 1;          // 0=r, 1=u
                    int dh  = sub & 1;
                    int d   = dh*32 + lane;
                    int b0 = listB[min(4*bq + 0, nB - 1)];
                    int b1 = listB[min(4*bq + 1, nB - 1)];
                    int b2 = listB[min(4*bq + 2, nB - 1)];
                    int b3 = listB[min(4*bq + 3, nB - 1)];
                    const float4* Wp = (const float4*)(Wst + g*KD132 + d*132);
                    const float4* p0 = (const float4*)(combs + b0*KR);
                    const float4* p1 = (const float4*)(combs + b1*KR);
                    const float4* p2 = (const float4*)(combs + b2*KR);
                    const float4* p3 = (const float4*)(combs + b3*KR);
                    float bias = beff_s[g*64 + d];
                    float a0 = bias, a1 = bias, a2 = bias, a3 = bias;
                    #pragma unroll 3
                    for (int k4 = 0; k4 < 33; k4++) {
                        float4 w  = Wp[k4];
                        float4 c0 = p0[k4], c1 = p1[k4], c2 = p2[k4], c3 = p3[k4];
                        a0 = fmaf(c0.x, w.x, a0); a0 = fmaf(c0.y, w.y, a0);
                        a0 = fmaf(c0.z, w.z, a0); a0 = fmaf(c0.w, w.w, a0);
                        a1 = fmaf(c1.x, w.x, a1); a1 = fmaf(c1.y, w.y, a1);
                        a1 = fmaf(c1.z, w.z, a1); a1 = fmaf(c1.w, w.w, a1);
                        a2 = fmaf(c2.x, w.x, a2); a2 = fmaf(c2.y, w.y, a2);
                        a2 = fmaf(c2.z, w.z, a2); a2 = fmaf(c2.w, w.w, a2);
                        a3 = fmaf(c3.x, w.x, a3); a3 = fmaf(c3.y, w.y, a3);
                        a3 = fmaf(c3.w, w.w, fmaf(c3.z, w.z, a3));
                    }
                    if (g == 0) {
                        zcs[b0*KR + 68 + d] = sigfast(a0) * hs[b0*64 + d];
                        zcs[b1*KR + 68 + d] = sigfast(a1) * hs[b1*64 + d];
                        zcs[b2*KR + 68 + d] = sigfast(a2) * hs[b2*64 + d];
                        zcs[b3*KR + 68 + d] = sigfast(a3) * hs[b3*64 + d];
                    } else {
                        us[b0*64 + d] = sigfast(a0);
                        us[b1*64 + d] = sigfast(a1);
                        us[b2*64 + d] = sigfast(a2);
                        us[b3*64 + d] = sigfast(a3);
                    }
                } else {
                    // candx octet: k = 0..64 on raw [x|rs]
                    int t2 = tau - NT_RU;
                    int bo = t2 >> 1;
                    int dh = t2 & 1;
                    int d  = dh*32 + lane;
                    int bb[8];
                    #pragma unroll
                    for (int i = 0; i < 8; i++) bb[i] = listB[min(8*bo + i, nB - 1)];
                    const float*  Wrow = Wst + 2*KD132 + d*132;
                    const float4* Wp   = (const float4*)Wrow;
                    const float4* z4   = (const float4*)zcs;
                    float bias = beff_s[2*64 + d];
                    float acc[8];
                    #pragma unroll
                    for (int i = 0; i < 8; i++) acc[i] = bias;
                    #pragma unroll 2
                    for (int k4 = 0; k4 < 16; k4++) {
                        float4 w = Wp[k4];
                        #pragma unroll
                        for (int i = 0; i < 8; i++) {
                            float4 c = z4[bb[i]*33 + k4];
                            acc[i] = fmaf(c.x, w.x, acc[i]);
                            acc[i] = fmaf(c.y, w.y, acc[i]);
                            acc[i] = fmaf(c.z, w.z, acc[i]);
                            acc[i] = fmaf(c.w, w.w, acc[i]);
                        }
                    }
                    float wrs = Wrow[64];
                    #pragma unroll
                    for (int i = 0; i < 8; i++) {
                        acc[i] = fmaf(zcs[bb[i]*KR + 64], wrs, acc[i]);
                        cxs[bb[i]*64 + d] = acc[i];
                    }
                }
            }
            __syncthreads();

            // ---- pass2: candh on batch-pairs; carry pairs after ----
            const int NT2 = 2*BP2 + ((B_ - nB + 1) >> 1);
            for (int tau = warp; tau < NT2; tau += 32) {
                if (tau < 2*BP2) {
                    int bp = tau >> 1;
                    int dh = tau & 1;
                    int d  = dh*32 + lane;
                    int b0 = listB[2*bp];
                    int b1 = listB[min(2*bp + 1, nB - 1)];
                    const float4* Wp = (const float4*)(Wst + 2*KD132 + d*132 + 68);
                    const float4* p0 = (const float4*)(zcs + b0*KR + 68);
                    const float4* p1 = (const float4*)(zcs + b1*KR + 68);
                    float a0 = cxs[b0*64 + d];
                    float a1 = cxs[b1*64 + d];
                    #pragma unroll 4
                    for (int k4 = 0; k4 < 16; k4++) {
                        float4 w  = Wp[k4];
                        float4 c0 = p0[k4], c1 = p1[k4];
                        a0 = fmaf(c0.x, w.x, a0); a0 = fmaf(c0.y, w.y, a0);
                        a0 = fmaf(c0.z, w.z, a0); a0 = fmaf(c0.w, w.w, a0);
                        a1 = fmaf(c1.x, w.x, a1); a1 = fmaf(c1.y, w.y, a1);
                        a1 = fmaf(c1.z, w.z, a1); a1 = fmaf(c1.w, w.w, a1);
                    }
                    float h10 = zcs[b0*KR + 68 + d];
                    float h11 = zcs[b1*KR + 68 + d];
                    float u0  = us[b0*64 + d];
                    float u1  = us[b1*64 + d];
                    float v0 = h10 + u0 * (tanhfast(a0) - h10);
                    float v1 = h11 + u1 * (tanhfast(a1) - h11);
                    hnext[(size_t)(b0*N_ + n)*D_ + d] = v0;
                    hnext[(size_t)(b1*N_ + n)*D_ + d] = v1;
                    if (t == lenS[b0] - 1) out[(size_t)(b0*N_ + n)*D_ + d] = v0;
                    if (t == lenS[b1] - 1) out[(size_t)(b1*N_ + n)*D_ + d] = v1;
                } else {
                    int iu = (tau - 2*BP2) * 2;
                    int nU = B_ - nB;
                    #pragma unroll
                    for (int rep = 0; rep < 2; rep++) {
                        if (iu + rep < nU) {
                            int b = listU[iu + rep];
                            int d0 = lane*2;
                            float2 v = *(const float2*)(hs + b*64 + d0);
                            *(float2*)(hnext + (size_t)(b*N_ + n)*D_ + d0) = v;
                            if (t == lenS[b] - 1)
                                *(float2*)(out + (size_t)(b*N_ + n)*D_ + d0) = v;
                        }
                    }
                }
            }
        }
        grid_barrier();
    }
}

extern "C" void kernel_launch(void* const* d_in, const int* in_sizes, int n_in,
                              void* d_out, int out_size) {
    const float* obs     = (const float*)d_in[0];
    const float* mask    = (const float*)d_in[2];
    const int*   lengths = (const int*)d_in[5];
    const float* avg     = (const float*)d_in[6];
    const float* vpe     = (const float*)d_in[7];
    const float* rarW    = (const float*)d_in[8];
    const float* adjI    = (const float*)d_in[9];
    const float* W1      = (const float*)d_in[10];
    const float* b1      = (const float*)d_in[11];
    const float* W2      = (const float*)d_in[12];
    const float* b2      = (const float*)d_in[13];
    const float* Wu      = (const float*)d_in[14];
    const float* bu      = (const float*)d_in[15];
    const float* Wr      = (const float*)d_in[16];
    const float* br      = (const float*)d_in[17];
    const float* Wc      = (const float*)d_in[18];
    const float* bc      = (const float*)d_in[19];
    float* out = (float*)d_out;

    cudaFuncSetAttribute(cgrnn_persistent,
                         cudaFuncAttributeMaxDynamicSharedMemorySize, SMEM_BYTES);
    cgrnn_persistent<<<GRID, BLOCK, SMEM_BYTES>>>(
        obs, mask, lengths, avg, vpe, rarW, adjI,
        W1, b1, W2, b2, Wr, br, Wu, bu, Wc, bc, out);
}